// round 2
// baseline (speedup 1.0000x reference)
#include <cuda_runtime.h>
#include <math_constants.h>

// Problem constants (fixed by the reference)
#define NM   32      // molecules
#define NA   40      // atoms per molecule
#define NSPEC 4
#define NPAIRS 10    // NSPEC*(NSPEC+1)/2
#define NRAD 16      // radial shifts
#define NANG 32      // 4 shf_a * 8 shf_z
#define FEAT 384     // 4*16 + 10*32
#define RCR  5.2f
#define RCA  3.5f
#define MAXP (NA*(NA-1)/2)   // 780 worst-case angular pairs

__global__ __launch_bounds__(384, 4)
void aev_kernel(const int* __restrict__ elem,
                const float* __restrict__ coords,
                float* __restrict__ out)
{
    const int bid = blockIdx.x;         // m*NA + i
    const int m   = bid / NA;
    const int i   = bid % NA;
    const int tid = threadIdx.x;

    __shared__ float sdx[NA], sdy[NA], sdz[NA], sd[NA], sfcR[NA], sfcA[NA];
    __shared__ int   selem[NA];
    __shared__ int   listR[NA], listA[NA];
    __shared__ int   cntR, cntA, npair;
    __shared__ float pca[MAXP], psa[MAXP], prm[MAXP], pfc[MAXP];
    __shared__ int   ppid[MAXP];

    // center atom coordinates (broadcast load, L1-cached)
    const float xi = coords[(m*NA + i)*3 + 0];
    const float yi = coords[(m*NA + i)*3 + 1];
    const float zi = coords[(m*NA + i)*3 + 2];

    // Phase 1: per-neighbor geometry
    if (tid < NA) {
        const float* cj = coords + (m*NA + tid)*3;
        float dx = cj[0] - xi;
        float dy = cj[1] - yi;
        float dz = cj[2] - zi;
        float d  = sqrtf(dx*dx + dy*dy + dz*dz + 1e-12f);
        sdx[tid] = dx; sdy[tid] = dy; sdz[tid] = dz; sd[tid] = d;
        sfcR[tid] = 0.5f * __cosf((CUDART_PI_F / RCR) * d) + 0.5f;
        sfcA[tid] = 0.5f * __cosf((CUDART_PI_F / RCA) * d) + 0.5f;
        selem[tid] = elem[m*NA + tid];
    }
    __syncthreads();

    // Phase 2: deterministic compact neighbor lists (serial, 40 iters)
    if (tid == 0) {
        int cr = 0, ca = 0;
        for (int j = 0; j < NA; j++) {
            if (j == i) continue;
            if (sd[j] < RCR) listR[cr++] = j;
            if (sd[j] < RCA) listA[ca++] = j;
        }
        cntR = cr; cntA = ca; npair = ca*(ca-1)/2;
    }
    __syncthreads();

    // Phase 3: per-pair invariants
    const int np = npair;
    const int ca_cnt = cntA;
    for (int p = tid; p < np; p += blockDim.x) {
        // decode (jj, kk), jj < kk over compact (ascending) list
        int jj = 0, rem = p, row = ca_cnt - 1;
        while (rem >= row) { rem -= row; row--; jj++; }
        int kk = jj + 1 + rem;
        int j = listA[jj], k = listA[kk];
        float dot = sdx[j]*sdx[k] + sdy[j]*sdy[k] + sdz[j]*sdz[k];
        float c   = 0.95f * dot / (sd[j] * sd[k]);   // |c| <= 0.95
        pca[p] = c;
        psa[p] = sqrtf(1.0f - c*c);                  // sin(acos(c)) >= 0
        prm[p] = 0.5f * (sd[j] + sd[k]);
        pfc[p] = sfcA[j] * sfcA[k];
        int e1 = selem[j], e2 = selem[k];
        int lo = min(e1, e2), hi = max(e1, e2);
        ppid[p] = lo*NSPEC - (lo*(lo-1))/2 + (hi - lo);
    }
    __syncthreads();

    float* o = out + bid * FEAT;

    if (tid < 64) {
        // Radial: feature (species s, shift fr), deterministic loop over listR
        const int s  = tid >> 4;
        const int fr = tid & 15;
        const float shf = 0.9f + 0.26875f * (float)fr;   // linspace(0.9,5.2,17)[:-1]
        float acc = 0.0f;
        const int cr = cntR;
        for (int n = 0; n < cr; n++) {
            int j = listR[n];
            if (selem[j] == s) {
                float dd = sd[j] - shf;
                acc += 0.25f * __expf(-16.0f * dd * dd) * sfcR[j];
            }
        }
        o[tid] = acc;
    } else {
        // Angular: feature (species-pair p10, shf_a a, shf_z t).
        // p10 is constant within each aligned warp -> filter is divergence-free.
        const int f   = tid - 64;
        const int p10 = f >> 5;
        const int rem = f & 31;
        const int a   = rem >> 3;
        const int t   = rem & 7;
        const float shfa = 0.9f + 0.65f * (float)a;      // {0.9,1.55,2.2,2.85}
        const float z = (CUDART_PI_F / 16.0f) * (float)(2*t + 1);
        float sz, cz;
        sincosf(z, &sz, &cz);
        float acc = 0.0f;
        for (int p = 0; p < np; p++) {
            if (ppid[p] != p10) continue;
            float cth = pca[p]*cz + psa[p]*sz;           // cos(theta - z)
            float x   = 0.5f + 0.5f*cth;
            float x2  = x*x;
            float x4  = x2*x2;
            float x8  = x4*x4;
            float x16 = x8*x8;
            float x32 = x16*x16;                          // x^ZETA, ZETA=32
            float dr = prm[p] - shfa;
            acc += 2.0f * __expf(-8.0f * dr * dr) * x32 * pfc[p];
        }
        o[tid] = acc;
    }
}

extern "C" void kernel_launch(void* const* d_in, const int* in_sizes, int n_in,
                              void* d_out, int out_size)
{
    const int*   elem   = (const int*)  d_in[0];   // elem_idxs (M*A) int32
    const float* coords = (const float*)d_in[1];   // coords (M*A*3) float32
    float*       out    = (float*)d_out;           // (M*A*FEAT) float32
    (void)in_sizes; (void)n_in; (void)out_size;
    aev_kernel<<<NM * NA, 384>>>(elem, coords, out);
}

// round 3
// speedup vs baseline: 1.3467x; 1.3467x over previous
#include <cuda_runtime.h>
#include <math_constants.h>

// Problem constants (fixed by the reference)
#define NM   32      // molecules
#define NA   40      // atoms per molecule
#define NSPEC 4
#define FEAT 384     // 4*16 + 10*32
#define RCR  5.2f
#define RCA  3.5f
#define MAXP (NA*(NA-1)/2)   // 780 worst-case angular pairs
#define BLK  128

__global__ __launch_bounds__(BLK, 12)
void aev_kernel(const int* __restrict__ elem,
                const float* __restrict__ coords,
                float* __restrict__ out)
{
    const int bid = blockIdx.x;         // m*NA + i
    const int m   = bid / NA;
    const int i   = bid % NA;
    const int tid = threadIdx.x;

    __shared__ float sdx[NA], sdy[NA], sdz[NA], sd[NA], sfcR[NA], sfcA[NA];
    __shared__ int   selem[NA];
    __shared__ int   listR[NA], listA[NA];
    __shared__ unsigned mR[2], mA[2];
    __shared__ float pca[MAXP], psa[MAXP], prm[MAXP], pfc[MAXP];
    __shared__ int   ppid[MAXP];

    // center atom coordinates (broadcast, L1-cached)
    const float xi = coords[(m*NA + i)*3 + 0];
    const float yi = coords[(m*NA + i)*3 + 1];
    const float zi = coords[(m*NA + i)*3 + 2];

    // Phase 1: per-neighbor geometry + ballot membership (parallel, no serial scan)
    bool inR = false, inA = false;
    if (tid < NA) {
        const float* cj = coords + (m*NA + tid)*3;
        float dx = cj[0] - xi;
        float dy = cj[1] - yi;
        float dz = cj[2] - zi;
        float d  = sqrtf(dx*dx + dy*dy + dz*dz + 1e-12f);
        sdx[tid] = dx; sdy[tid] = dy; sdz[tid] = dz; sd[tid] = d;
        sfcR[tid] = 0.5f * __cosf((CUDART_PI_F / RCR) * d) + 0.5f;
        sfcA[tid] = 0.5f * __cosf((CUDART_PI_F / RCA) * d) + 0.5f;
        selem[tid] = elem[m*NA + tid];
        inR = (tid != i) && (d < RCR);
        inA = (tid != i) && (d < RCA);
        const unsigned act = (tid < 32) ? 0xFFFFFFFFu : 0x000000FFu;
        unsigned bR = __ballot_sync(act, inR);
        unsigned bA = __ballot_sync(act, inA);
        int w = tid >> 5;
        if ((tid & 31) == 0) { mR[w] = bR; mA[w] = bA; }
    }
    __syncthreads();

    // Uniform counts from masks (every thread computes its own copy)
    const int cntR = __popc(mR[0]) + __popc(mR[1]);
    const int cntA = __popc(mA[0]) + __popc(mA[1]);
    const int np   = cntA * (cntA - 1) / 2;

    // Phase 2: scatter into compact ascending lists via popc prefix
    if (tid < NA) {
        const unsigned lt = (1u << (tid & 31)) - 1u;
        const int w = tid >> 5;
        if (inR) {
            int pos = (w ? __popc(mR[0]) : 0) + __popc(mR[w] & lt);
            listR[pos] = tid;
        }
        if (inA) {
            int pos = (w ? __popc(mA[0]) : 0) + __popc(mA[w] & lt);
            listA[pos] = tid;
        }
    }
    __syncthreads();

    // Phase 3: per-pair invariants (jj < kk over compact ascending list)
    for (int p = tid; p < np; p += BLK) {
        int jj = 0, rem = p, row = cntA - 1;
        while (rem >= row) { rem -= row; row--; jj++; }
        int kk = jj + 1 + rem;
        int j = listA[jj], k = listA[kk];
        float dot = sdx[j]*sdx[k] + sdy[j]*sdy[k] + sdz[j]*sdz[k];
        float c   = 0.95f * dot / (sd[j] * sd[k]);   // |c| <= 0.95
        pca[p] = c;
        psa[p] = sqrtf(1.0f - c*c);                  // sin(acos(c)) >= 0
        prm[p] = 0.5f * (sd[j] + sd[k]);
        pfc[p] = sfcA[j] * sfcA[k];
        int e1 = selem[j], e2 = selem[k];
        int lo = min(e1, e2), hi = max(e1, e2);
        ppid[p] = lo*NSPEC - (lo*(lo-1))/2 + (hi - lo);
    }
    __syncthreads();

    // Phase 4: each thread owns 3 features (f = tid, tid+128, tid+256).
    // Feature blocks of 32 stay warp-aligned -> angular p10 filter is warp-uniform.
    float* o = out + bid * FEAT;
    #pragma unroll
    for (int f = tid; f < FEAT; f += BLK) {
        float acc = 0.0f;
        if (f < 64) {
            // Radial: (species s, shift fr)
            const int s  = f >> 4;
            const int fr = f & 15;
            const float shf = 0.9f + 0.26875f * (float)fr;
            for (int n = 0; n < cntR; n++) {
                int j = listR[n];
                if (selem[j] == s) {
                    float dd = sd[j] - shf;
                    acc += 0.25f * __expf(-16.0f * dd * dd) * sfcR[j];
                }
            }
        } else {
            // Angular: (species-pair p10, shf_a a, shf_z t)
            const int g   = f - 64;
            const int p10 = g >> 5;
            const int rem = g & 31;
            const int a   = rem >> 3;
            const int t   = rem & 7;
            const float shfa = 0.9f + 0.65f * (float)a;
            const float z = (CUDART_PI_F / 16.0f) * (float)(2*t + 1);
            float sz, cz;
            __sincosf(z, &sz, &cz);
            for (int p = 0; p < np; p++) {
                if (ppid[p] != p10) continue;
                float cth = pca[p]*cz + psa[p]*sz;    // cos(theta - z)
                float x   = 0.5f + 0.5f*cth;
                float x2  = x*x;
                float x4  = x2*x2;
                float x8  = x4*x4;
                float x16 = x8*x8;
                float x32 = x16*x16;                   // x^ZETA, ZETA=32
                float dr = prm[p] - shfa;
                acc += 2.0f * __expf(-8.0f * dr * dr) * x32 * pfc[p];
            }
        }
        o[f] = acc;
    }
}

extern "C" void kernel_launch(void* const* d_in, const int* in_sizes, int n_in,
                              void* d_out, int out_size)
{
    const int*   elem   = (const int*)  d_in[0];   // elem_idxs (M*A) int32
    const float* coords = (const float*)d_in[1];   // coords (M*A*3) float32
    float*       out    = (float*)d_out;           // (M*A*FEAT) float32
    (void)in_sizes; (void)n_in; (void)out_size;
    aev_kernel<<<NM * NA, BLK>>>(elem, coords, out);
}